// round 15
// baseline (speedup 1.0000x reference)
#include <cuda_runtime.h>
#include <cuda_bf16.h>
#include <cuda_fp16.h>
#include <math.h>
#include <stdint.h>

#define MAX_N 50000
#define DIM 128
#define RS 272          // padded row stride in BYTES for fp16 tiles (136 elems)

// ---------------------------------------------------------------------------
// Scratch (.bss device globals, no allocations)
// ---------------------------------------------------------------------------
__device__ float g_Y[MAX_N * DIM];                  // global half: x @ Wg^T (fp32)
__device__ __align__(16) __half2 g_Yc[MAX_N * 64];  // combined half: x @ (Wg+Wl)^T (fp16)
__device__ int   g_rowptr[MAX_N + 1];               // CSR offsets into sorted seg_ids

// ---------------------------------------------------------------------------
// PTX helpers
// ---------------------------------------------------------------------------
static __device__ __forceinline__ uint32_t smem_u32(const void* p) {
    uint32_t a;
    asm("{ .reg .u64 t; cvta.to.shared.u64 t, %1; cvt.u32.u64 %0, t; }" : "=r"(a) : "l"(p));
    return a;
}

#define LDSM_X4(R, ADDR)                                                     \
    asm volatile("ldmatrix.sync.aligned.m8n8.x4.shared.b16 {%0,%1,%2,%3}, [%4];" \
                 : "=r"((R)[0]), "=r"((R)[1]), "=r"((R)[2]), "=r"((R)[3])    \
                 : "r"(ADDR))

#define MMA_FP16(D, A, B0, B1)                                               \
    asm volatile("mma.sync.aligned.m16n8k16.row.col.f32.f16.f16.f32 "       \
                 "{%0,%1,%2,%3}, {%4,%5,%6,%7}, {%8,%9}, {%0,%1,%2,%3};"     \
                 : "+f"((D)[0]), "+f"((D)[1]), "+f"((D)[2]), "+f"((D)[3])    \
                 : "r"((A)[0]), "r"((A)[1]), "r"((A)[2]), "r"((A)[3]),       \
                   "r"(B0), "r"(B1))

// ---------------------------------------------------------------------------
// Persistent HMMA GEMM, 512 threads, single-pass fp16 both halves.
// Prologue ALSO computes the CSR rowptr scatter (grid-stride over edges),
// overlapped with the DRAM-bound B/A tile loads. Nothing in this kernel
// reads g_rowptr; the gather kernel launches afterwards on the same stream.
//   global half  (-> g_Y fp32):  Af * fp16(Wg)
//   combined half(-> g_Yc fp16): Af * fp16(Wg+Wl)
// ---------------------------------------------------------------------------
#define SM_A0  0
#define SM_A1  34816
#define SM_BG  69632
#define SM_BC  104448
#define SM_TOTAL 139264
#define GTHREADS 512

__global__ __launch_bounds__(GTHREADS, 1) void gemm_tc_kernel(const float* __restrict__ A,
                                                              const float* __restrict__ Wg,
                                                              const float* __restrict__ Wl,
                                                              const int* __restrict__ sids,
                                                              int E,
                                                              int Nrows, int ntiles)
{
    extern __shared__ unsigned char smem[];
    const uint32_t sb = smem_u32(smem);
    const int tid  = threadIdx.x;
    const int wid  = tid >> 5;
    const int lane = tid & 31;

    // ---- rowptr scatter folded into prologue (overlaps DRAM loads below) ----
    {
        const int gstride = gridDim.x * GTHREADS;
        for (int e = blockIdx.x * GTHREADS + tid; e < E; e += gstride) {
            int cur  = __ldg(&sids[e]);
            int prev = (e == 0) ? -1 : __ldg(&sids[e - 1]);
            for (int n = prev + 1; n <= cur; n++)
                g_rowptr[n] = e;
            if (e == E - 1) {
                for (int n = cur + 1; n <= Nrows; n++)
                    g_rowptr[n] = E;
            }
        }
    }

    // ---- build B tiles in smem directly from Wg/Wl (once per CTA) ----
    {
        #pragma unroll
        for (int i = 0; i < 8; i++) {
            int u = tid + i * GTHREADS;       // 4096 float4 slots
            int j = u >> 5;                   // weight row (n) 0..127
            int q = u & 31;                   // float4 within k
            float4 vg = *reinterpret_cast<const float4*>(&Wg[j * DIM + 4 * q]);
            float4 vl = *reinterpret_cast<const float4*>(&Wl[j * DIM + 4 * q]);
            __half2 g0 = __floats2half2_rn(vg.x, vg.y);
            __half2 g1 = __floats2half2_rn(vg.z, vg.w);
            __half2 c0 = __floats2half2_rn(vg.x + vl.x, vg.y + vl.y);
            __half2 c1 = __floats2half2_rn(vg.z + vl.z, vg.w + vl.w);
            *reinterpret_cast<__half2*>(&smem[SM_BG + j * RS + q * 8])     = g0;
            *reinterpret_cast<__half2*>(&smem[SM_BG + j * RS + q * 8 + 4]) = g1;
            *reinterpret_cast<__half2*>(&smem[SM_BC + j * RS + q * 8])     = c0;
            *reinterpret_cast<__half2*>(&smem[SM_BC + j * RS + q * 8 + 4]) = c1;
        }
    }
    // visibility of B covered by the per-tile __syncthreads below

    // ---- warp mapping: warp_n = wid&7 (16-col group), warp_m = wid>>3 ----
    const int warp_n = wid & 7;
    const int warp_m = wid >> 3;          // 0 | 1 -> 64-row half

    // ---- per-lane ldmatrix address parts ----
    const uint32_t aPart = (uint32_t)(((warp_m * 64) + (lane & 15)) * RS + (lane >> 4) * 16);
    const uint32_t bPart = (uint32_t)(((lane & 7) + ((lane >> 4) << 3)) * RS
                                      + ((lane >> 3) & 1) * 16);
    const uint32_t bgF = sb + SM_BG + (uint32_t)(warp_n * 16) * RS + bPart;
    const uint32_t bcF = sb + SM_BC + (uint32_t)(warp_n * 16) * RS + bPart;

    const int g  = lane >> 2;
    const int tg = lane & 3;

    int buf = 0;
    for (int tile = blockIdx.x; tile < ntiles; tile += gridDim.x, buf ^= 1) {
        const int bm = tile * 128;
        const uint32_t aBase = buf ? SM_A1 : SM_A0;

        // ---- convert A tile fp32 -> fp16 into padded smem (8 iters x 512) ----
        #pragma unroll
        for (int i = 0; i < 8; i++) {
            int u = tid + i * GTHREADS;       // 4096 float4 slots
            int r = u >> 5;                   // row 0..127
            int q = u & 31;                   // float4 within row
            int row = bm + r;
            float4 v = make_float4(0.f, 0.f, 0.f, 0.f);
            if (row < Nrows)
                v = *reinterpret_cast<const float4*>(&A[row * DIM + 4 * q]);
            __half2 h0 = __floats2half2_rn(v.x, v.y);
            __half2 h1 = __floats2half2_rn(v.z, v.w);
            *reinterpret_cast<__half2*>(&smem[aBase + r * RS + q * 8])     = h0;
            *reinterpret_cast<__half2*>(&smem[aBase + r * RS + q * 8 + 4]) = h1;
        }
        __syncthreads();   // convert(i) + B visible; mainloop(i-1) drained

        const uint32_t aF = sb + aBase + aPart;

        float accG[4][2][4], accC[4][2][4];
        #pragma unroll
        for (int i = 0; i < 4; i++)
            #pragma unroll
            for (int j = 0; j < 2; j++)
                #pragma unroll
                for (int q = 0; q < 4; q++) { accG[i][j][q] = 0.f; accC[i][j][q] = 0.f; }

        #pragma unroll
        for (int ks = 0; ks < 8; ks++) {
            const uint32_t ko = (uint32_t)(ks * 32);   // 16 k * 2B
            uint32_t bg[4], bc[4];
            LDSM_X4(bg, bgF + ko);
            LDSM_X4(bc, bcF + ko);
            #pragma unroll
            for (int mf = 0; mf < 4; mf++) {
                uint32_t af[4];
                LDSM_X4(af, aF + (uint32_t)(mf * 16) * RS + ko);
                MMA_FP16(accG[mf][0], af, bg[0], bg[1]);
                MMA_FP16(accG[mf][1], af, bg[2], bg[3]);
                MMA_FP16(accC[mf][0], af, bc[0], bc[1]);
                MMA_FP16(accC[mf][1], af, bc[2], bc[3]);
            }
        }

        // ---- store: global -> g_Y fp32, combined -> g_Yc fp16 ----
        #pragma unroll
        for (int mf = 0; mf < 4; mf++) {
            int row0 = bm + warp_m * 64 + mf * 16 + g;
            int row1 = row0 + 8;
            #pragma unroll
            for (int nf = 0; nf < 2; nf++) {
                int col = warp_n * 16 + nf * 8 + tg * 2;    // 0..127, even
                if (row0 < Nrows) {
                    *reinterpret_cast<float2*>(&g_Y[row0 * DIM + col]) =
                        make_float2(accG[mf][nf][0], accG[mf][nf][1]);
                    g_Yc[row0 * 64 + (col >> 1)] =
                        __floats2half2_rn(accC[mf][nf][0], accC[mf][nf][1]);
                }
                if (row1 < Nrows) {
                    *reinterpret_cast<float2*>(&g_Y[row1 * DIM + col]) =
                        make_float2(accG[mf][nf][2], accG[mf][nf][3]);
                    g_Yc[row1 * 64 + (col >> 1)] =
                        __floats2half2_rn(accC[mf][nf][2], accC[mf][nf][3]);
                }
            }
        }
    }
}

// ---------------------------------------------------------------------------
// Gather (frozen): one warp per node; half-warp per edge; 8-edge unroll;
// fp32 accumulation; direct idx loads; shfl_xor(16) combine.
// ---------------------------------------------------------------------------
__device__ __forceinline__ void acc_row(float* acc, const uint4& u)
{
    float2 p0 = __half22float2(*reinterpret_cast<const __half2*>(&u.x));
    float2 p1 = __half22float2(*reinterpret_cast<const __half2*>(&u.y));
    float2 p2 = __half22float2(*reinterpret_cast<const __half2*>(&u.z));
    float2 p3 = __half22float2(*reinterpret_cast<const __half2*>(&u.w));
    acc[0] += p0.x; acc[1] += p0.y; acc[2] += p1.x; acc[3] += p1.y;
    acc[4] += p2.x; acc[5] += p2.y; acc[6] += p3.x; acc[7] += p3.y;
}

__global__ __launch_bounds__(256) void gather_kernel(const int* __restrict__ nidx,
                                                     const float* __restrict__ bias,
                                                     float* __restrict__ out, int N)
{
    int warp = (blockIdx.x * blockDim.x + threadIdx.x) >> 5;
    int lane = threadIdx.x & 31;
    if (warp >= N) return;

    const int half = lane >> 4;      // 0 | 1
    const int hl   = lane & 15;      // lane within half-warp

    int s = g_rowptr[warp];
    int e = g_rowptr[warp + 1];

    float acc[8];
    #pragma unroll
    for (int q = 0; q < 8; q++) acc[q] = 0.f;

    int j = s;
    for (; j + 8 <= e; j += 8) {
        int i0 = __ldg(&nidx[j + half]);
        int i1 = __ldg(&nidx[j + 2 + half]);
        int i2 = __ldg(&nidx[j + 4 + half]);
        int i3 = __ldg(&nidx[j + 6 + half]);
        uint4 u0 = *reinterpret_cast<const uint4*>(&g_Yc[i0 * 64 + hl * 4]);
        uint4 u1 = *reinterpret_cast<const uint4*>(&g_Yc[i1 * 64 + hl * 4]);
        uint4 u2 = *reinterpret_cast<const uint4*>(&g_Yc[i2 * 64 + hl * 4]);
        uint4 u3 = *reinterpret_cast<const uint4*>(&g_Yc[i3 * 64 + hl * 4]);
        acc_row(acc, u0);
        acc_row(acc, u1);
        acc_row(acc, u2);
        acc_row(acc, u3);
    }
    for (; j + 2 <= e; j += 2) {
        int i0 = __ldg(&nidx[j + half]);
        uint4 u0 = *reinterpret_cast<const uint4*>(&g_Yc[i0 * 64 + hl * 4]);
        acc_row(acc, u0);
    }
    if (j < e && half == 0) {
        int i0 = __ldg(&nidx[j]);
        uint4 u0 = *reinterpret_cast<const uint4*>(&g_Yc[i0 * 64 + hl * 4]);
        acc_row(acc, u0);
    }

    // combine the two half-warps
    #pragma unroll
    for (int q = 0; q < 8; q++)
        acc[q] += __shfl_xor_sync(0xffffffffu, acc[q], 16);

    int cnt = e - s;
    float inv = (cnt > 0) ? (1.0f / (float)cnt) : 0.f;
    int d = hl * 8 + half * 4;
    const float* ap = &acc[half * 4];

    float4 g = *reinterpret_cast<const float4*>(&g_Y[warp * DIM + d]);
    float4 b = *reinterpret_cast<const float4*>(&bias[d]);

    float4 o;
    o.x = ((cnt > 0) ? ap[0] * inv : g.x) + g.x + b.x;
    o.y = ((cnt > 0) ? ap[1] * inv : g.y) + g.y + b.y;
    o.z = ((cnt > 0) ? ap[2] * inv : g.z) + g.z + b.z;
    o.w = ((cnt > 0) ? ap[3] * inv : g.w) + g.w + b.w;
    o.x = (o.x > 0.f) ? o.x : expm1f(o.x);
    o.y = (o.y > 0.f) ? o.y : expm1f(o.y);
    o.z = (o.z > 0.f) ? o.z : expm1f(o.z);
    o.w = (o.w > 0.f) ? o.w : expm1f(o.w);

    *reinterpret_cast<float4*>(&out[warp * DIM + d]) = o;
}

// ---------------------------------------------------------------------------
extern "C" void kernel_launch(void* const* d_in, const int* in_sizes, int n_in,
                              void* d_out, int out_size)
{
    const float* x    = (const float*)d_in[0];
    const float* Wg   = (const float*)d_in[1];
    const float* Wl   = (const float*)d_in[2];
    const float* bias = (const float*)d_in[3];
    const int*   nidx = (const int*)d_in[4];
    const int*   sids = (const int*)d_in[5];
    float* out = (float*)d_out;

    const int N = in_sizes[0] / DIM;
    const int E = in_sizes[4];

    cudaFuncSetAttribute(gemm_tc_kernel, cudaFuncAttributeMaxDynamicSharedMemorySize, SM_TOTAL);

    const int ntiles = (N + 127) / 128;
    const int grid = ntiles < 148 ? ntiles : 148;
    gemm_tc_kernel<<<grid, GTHREADS, SM_TOTAL>>>(x, Wg, Wl, sids, E, N, ntiles);

    int blocks = (N * 32 + 255) / 256;
    gather_kernel<<<blocks, 256>>>(nidx, bias, out, N);
}

// round 16
// speedup vs baseline: 1.0360x; 1.0360x over previous
#include <cuda_runtime.h>
#include <cuda_bf16.h>
#include <cuda_fp16.h>
#include <math.h>
#include <stdint.h>

#define MAX_N 50000
#define DIM 128
#define RS 272          // padded row stride in BYTES for fp16 tiles (136 elems)

// ---------------------------------------------------------------------------
// Scratch (.bss device globals, no allocations)
// ---------------------------------------------------------------------------
__device__ float g_Y[MAX_N * DIM];                  // global half: x @ Wg^T (fp32)
__device__ __align__(16) __half2 g_Yc[MAX_N * 64];  // combined half: x @ (Wg+Wl)^T (fp16)
__device__ int   g_rowptr[MAX_N + 1];               // CSR offsets into sorted seg_ids

// ---------------------------------------------------------------------------
// PTX helpers
// ---------------------------------------------------------------------------
static __device__ __forceinline__ uint32_t smem_u32(const void* p) {
    uint32_t a;
    asm("{ .reg .u64 t; cvta.to.shared.u64 t, %1; cvt.u32.u64 %0, t; }" : "=r"(a) : "l"(p));
    return a;
}

#define LDSM_X4(R, ADDR)                                                     \
    asm volatile("ldmatrix.sync.aligned.m8n8.x4.shared.b16 {%0,%1,%2,%3}, [%4];" \
                 : "=r"((R)[0]), "=r"((R)[1]), "=r"((R)[2]), "=r"((R)[3])    \
                 : "r"(ADDR))

#define MMA_FP16(D, A, B0, B1)                                               \
    asm volatile("mma.sync.aligned.m16n8k16.row.col.f32.f16.f16.f32 "       \
                 "{%0,%1,%2,%3}, {%4,%5,%6,%7}, {%8,%9}, {%0,%1,%2,%3};"     \
                 : "+f"((D)[0]), "+f"((D)[1]), "+f"((D)[2]), "+f"((D)[3])    \
                 : "r"((A)[0]), "r"((A)[1]), "r"((A)[2]), "r"((A)[3]),       \
                   "r"(B0), "r"(B1))

// ---------------------------------------------------------------------------
// Persistent HMMA GEMM, 512 threads, single-pass fp16 both halves.
// Prologue also computes the CSR rowptr scatter, CHUNKED x4 for MLP:
// batch 4 independent (cur, prev) loads, then scatter — ~3 exposed DRAM
// latencies instead of ~11. Nothing here reads g_rowptr; gather launches
// after GEMM on the same stream.
//   global half  (-> g_Y fp32):  Af * fp16(Wg)
//   combined half(-> g_Yc fp16): Af * fp16(Wg+Wl)
// ---------------------------------------------------------------------------
#define SM_A0  0
#define SM_A1  34816
#define SM_BG  69632
#define SM_BC  104448
#define SM_TOTAL 139264
#define GTHREADS 512

__global__ __launch_bounds__(GTHREADS, 1) void gemm_tc_kernel(const float* __restrict__ A,
                                                              const float* __restrict__ Wg,
                                                              const float* __restrict__ Wl,
                                                              const int* __restrict__ sids,
                                                              int E,
                                                              int Nrows, int ntiles)
{
    extern __shared__ unsigned char smem[];
    const uint32_t sb = smem_u32(smem);
    const int tid  = threadIdx.x;
    const int wid  = tid >> 5;
    const int lane = tid & 31;

    // ---- rowptr scatter, chunked x4 for memory-level parallelism ----
    {
        const int gstride = gridDim.x * GTHREADS;
        const int e0 = blockIdx.x * GTHREADS + tid;
        for (int base = e0; base < E; base += 4 * gstride) {
            int cc[4], pp[4];
            #pragma unroll
            for (int t = 0; t < 4; t++) {
                int e = base + t * gstride;
                if (e < E) {
                    cc[t] = __ldg(&sids[e]);
                    pp[t] = (e == 0) ? -1 : __ldg(&sids[e - 1]);
                }
            }
            #pragma unroll
            for (int t = 0; t < 4; t++) {
                int e = base + t * gstride;
                if (e < E) {
                    for (int n = pp[t] + 1; n <= cc[t]; n++)
                        g_rowptr[n] = e;
                    if (e == E - 1) {
                        for (int n = cc[t] + 1; n <= Nrows; n++)
                            g_rowptr[n] = E;
                    }
                }
            }
        }
    }

    // ---- build B tiles in smem directly from Wg/Wl (once per CTA) ----
    {
        #pragma unroll
        for (int i = 0; i < 8; i++) {
            int u = tid + i * GTHREADS;       // 4096 float4 slots
            int j = u >> 5;                   // weight row (n) 0..127
            int q = u & 31;                   // float4 within k
            float4 vg = *reinterpret_cast<const float4*>(&Wg[j * DIM + 4 * q]);
            float4 vl = *reinterpret_cast<const float4*>(&Wl[j * DIM + 4 * q]);
            __half2 g0 = __floats2half2_rn(vg.x, vg.y);
            __half2 g1 = __floats2half2_rn(vg.z, vg.w);
            __half2 c0 = __floats2half2_rn(vg.x + vl.x, vg.y + vl.y);
            __half2 c1 = __floats2half2_rn(vg.z + vl.z, vg.w + vl.w);
            *reinterpret_cast<__half2*>(&smem[SM_BG + j * RS + q * 8])     = g0;
            *reinterpret_cast<__half2*>(&smem[SM_BG + j * RS + q * 8 + 4]) = g1;
            *reinterpret_cast<__half2*>(&smem[SM_BC + j * RS + q * 8])     = c0;
            *reinterpret_cast<__half2*>(&smem[SM_BC + j * RS + q * 8 + 4]) = c1;
        }
    }
    // visibility of B covered by the per-tile __syncthreads below

    // ---- warp mapping: warp_n = wid&7 (16-col group), warp_m = wid>>3 ----
    const int warp_n = wid & 7;
    const int warp_m = wid >> 3;          // 0 | 1 -> 64-row half

    // ---- per-lane ldmatrix address parts ----
    const uint32_t aPart = (uint32_t)(((warp_m * 64) + (lane & 15)) * RS + (lane >> 4) * 16);
    const uint32_t bPart = (uint32_t)(((lane & 7) + ((lane >> 4) << 3)) * RS
                                      + ((lane >> 3) & 1) * 16);
    const uint32_t bgF = sb + SM_BG + (uint32_t)(warp_n * 16) * RS + bPart;
    const uint32_t bcF = sb + SM_BC + (uint32_t)(warp_n * 16) * RS + bPart;

    const int g  = lane >> 2;
    const int tg = lane & 3;

    int buf = 0;
    for (int tile = blockIdx.x; tile < ntiles; tile += gridDim.x, buf ^= 1) {
        const int bm = tile * 128;
        const uint32_t aBase = buf ? SM_A1 : SM_A0;

        // ---- convert A tile fp32 -> fp16 into padded smem (8 iters x 512) ----
        #pragma unroll
        for (int i = 0; i < 8; i++) {
            int u = tid + i * GTHREADS;       // 4096 float4 slots
            int r = u >> 5;                   // row 0..127
            int q = u & 31;                   // float4 within row
            int row = bm + r;
            float4 v = make_float4(0.f, 0.f, 0.f, 0.f);
            if (row < Nrows)
                v = *reinterpret_cast<const float4*>(&A[row * DIM + 4 * q]);
            __half2 h0 = __floats2half2_rn(v.x, v.y);
            __half2 h1 = __floats2half2_rn(v.z, v.w);
            *reinterpret_cast<__half2*>(&smem[aBase + r * RS + q * 8])     = h0;
            *reinterpret_cast<__half2*>(&smem[aBase + r * RS + q * 8 + 4]) = h1;
        }
        __syncthreads();   // convert(i) + B visible; mainloop(i-1) drained

        const uint32_t aF = sb + aBase + aPart;

        float accG[4][2][4], accC[4][2][4];
        #pragma unroll
        for (int i = 0; i < 4; i++)
            #pragma unroll
            for (int j = 0; j < 2; j++)
                #pragma unroll
                for (int q = 0; q < 4; q++) { accG[i][j][q] = 0.f; accC[i][j][q] = 0.f; }

        #pragma unroll
        for (int ks = 0; ks < 8; ks++) {
            const uint32_t ko = (uint32_t)(ks * 32);   // 16 k * 2B
            uint32_t bg[4], bc[4];
            LDSM_X4(bg, bgF + ko);
            LDSM_X4(bc, bcF + ko);
            #pragma unroll
            for (int mf = 0; mf < 4; mf++) {
                uint32_t af[4];
                LDSM_X4(af, aF + (uint32_t)(mf * 16) * RS + ko);
                MMA_FP16(accG[mf][0], af, bg[0], bg[1]);
                MMA_FP16(accG[mf][1], af, bg[2], bg[3]);
                MMA_FP16(accC[mf][0], af, bc[0], bc[1]);
                MMA_FP16(accC[mf][1], af, bc[2], bc[3]);
            }
        }

        // ---- store: global -> g_Y fp32, combined -> g_Yc fp16 ----
        #pragma unroll
        for (int mf = 0; mf < 4; mf++) {
            int row0 = bm + warp_m * 64 + mf * 16 + g;
            int row1 = row0 + 8;
            #pragma unroll
            for (int nf = 0; nf < 2; nf++) {
                int col = warp_n * 16 + nf * 8 + tg * 2;    // 0..127, even
                if (row0 < Nrows) {
                    *reinterpret_cast<float2*>(&g_Y[row0 * DIM + col]) =
                        make_float2(accG[mf][nf][0], accG[mf][nf][1]);
                    g_Yc[row0 * 64 + (col >> 1)] =
                        __floats2half2_rn(accC[mf][nf][0], accC[mf][nf][1]);
                }
                if (row1 < Nrows) {
                    *reinterpret_cast<float2*>(&g_Y[row1 * DIM + col]) =
                        make_float2(accG[mf][nf][2], accG[mf][nf][3]);
                    g_Yc[row1 * 64 + (col >> 1)] =
                        __floats2half2_rn(accC[mf][nf][2], accC[mf][nf][3]);
                }
            }
        }
    }
}

// ---------------------------------------------------------------------------
// Gather (frozen): one warp per node; half-warp per edge; 8-edge unroll;
// fp32 accumulation; direct idx loads; shfl_xor(16) combine.
// ---------------------------------------------------------------------------
__device__ __forceinline__ void acc_row(float* acc, const uint4& u)
{
    float2 p0 = __half22float2(*reinterpret_cast<const __half2*>(&u.x));
    float2 p1 = __half22float2(*reinterpret_cast<const __half2*>(&u.y));
    float2 p2 = __half22float2(*reinterpret_cast<const __half2*>(&u.z));
    float2 p3 = __half22float2(*reinterpret_cast<const __half2*>(&u.w));
    acc[0] += p0.x; acc[1] += p0.y; acc[2] += p1.x; acc[3] += p1.y;
    acc[4] += p2.x; acc[5] += p2.y; acc[6] += p3.x; acc[7] += p3.y;
}

__global__ __launch_bounds__(256) void gather_kernel(const int* __restrict__ nidx,
                                                     const float* __restrict__ bias,
                                                     float* __restrict__ out, int N)
{
    int warp = (blockIdx.x * blockDim.x + threadIdx.x) >> 5;
    int lane = threadIdx.x & 31;
    if (warp >= N) return;

    const int half = lane >> 4;      // 0 | 1
    const int hl   = lane & 15;      // lane within half-warp

    int s = g_rowptr[warp];
    int e = g_rowptr[warp + 1];

    float acc[8];
    #pragma unroll
    for (int q = 0; q < 8; q++) acc[q] = 0.f;

    int j = s;
    for (; j + 8 <= e; j += 8) {
        int i0 = __ldg(&nidx[j + half]);
        int i1 = __ldg(&nidx[j + 2 + half]);
        int i2 = __ldg(&nidx[j + 4 + half]);
        int i3 = __ldg(&nidx[j + 6 + half]);
        uint4 u0 = *reinterpret_cast<const uint4*>(&g_Yc[i0 * 64 + hl * 4]);
        uint4 u1 = *reinterpret_cast<const uint4*>(&g_Yc[i1 * 64 + hl * 4]);
        uint4 u2 = *reinterpret_cast<const uint4*>(&g_Yc[i2 * 64 + hl * 4]);
        uint4 u3 = *reinterpret_cast<const uint4*>(&g_Yc[i3 * 64 + hl * 4]);
        acc_row(acc, u0);
        acc_row(acc, u1);
        acc_row(acc, u2);
        acc_row(acc, u3);
    }
    for (; j + 2 <= e; j += 2) {
        int i0 = __ldg(&nidx[j + half]);
        uint4 u0 = *reinterpret_cast<const uint4*>(&g_Yc[i0 * 64 + hl * 4]);
        acc_row(acc, u0);
    }
    if (j < e && half == 0) {
        int i0 = __ldg(&nidx[j]);
        uint4 u0 = *reinterpret_cast<const uint4*>(&g_Yc[i0 * 64 + hl * 4]);
        acc_row(acc, u0);
    }

    // combine the two half-warps
    #pragma unroll
    for (int q = 0; q < 8; q++)
        acc[q] += __shfl_xor_sync(0xffffffffu, acc[q], 16);

    int cnt = e - s;
    float inv = (cnt > 0) ? (1.0f / (float)cnt) : 0.f;
    int d = hl * 8 + half * 4;
    const float* ap = &acc[half * 4];

    float4 g = *reinterpret_cast<const float4*>(&g_Y[warp * DIM + d]);
    float4 b = *reinterpret_cast<const float4*>(&bias[d]);

    float4 o;
    o.x = ((cnt > 0) ? ap[0] * inv : g.x) + g.x + b.x;
    o.y = ((cnt > 0) ? ap[1] * inv : g.y) + g.y + b.y;
    o.z = ((cnt > 0) ? ap[2] * inv : g.z) + g.z + b.z;
    o.w = ((cnt > 0) ? ap[3] * inv : g.w) + g.w + b.w;
    o.x = (o.x > 0.f) ? o.x : expm1f(o.x);
    o.y = (o.y > 0.f) ? o.y : expm1f(o.y);
    o.z = (o.z > 0.f) ? o.z : expm1f(o.z);
    o.w = (o.w > 0.f) ? o.w : expm1f(o.w);

    *reinterpret_cast<float4*>(&out[warp * DIM + d]) = o;
}

// ---------------------------------------------------------------------------
extern "C" void kernel_launch(void* const* d_in, const int* in_sizes, int n_in,
                              void* d_out, int out_size)
{
    const float* x    = (const float*)d_in[0];
    const float* Wg   = (const float*)d_in[1];
    const float* Wl   = (const float*)d_in[2];
    const float* bias = (const float*)d_in[3];
    const int*   nidx = (const int*)d_in[4];
    const int*   sids = (const int*)d_in[5];
    float* out = (float*)d_out;

    const int N = in_sizes[0] / DIM;
    const int E = in_sizes[4];

    cudaFuncSetAttribute(gemm_tc_kernel, cudaFuncAttributeMaxDynamicSharedMemorySize, SM_TOTAL);

    const int ntiles = (N + 127) / 128;
    const int grid = ntiles < 148 ? ntiles : 148;
    gemm_tc_kernel<<<grid, GTHREADS, SM_TOTAL>>>(x, Wg, Wl, sids, E, N, ntiles);

    int blocks = (N * 32 + 255) / 256;
    gather_kernel<<<blocks, 256>>>(nidx, bias, out, N);
}